// round 13
// baseline (speedup 1.0000x reference)
#include <cuda_runtime.h>
#include <cuda_fp16.h>
#include <cstdint>

// ============================================================================
// QLoRABigNet on GB300 (mma.sync fp16, 2-pass Karatsuba split, LN folded)
//   activations/weights stored as (h, u):  h = fl16(x), u = fl16(h + 32*(x-h))
//   y = P1 + (P2 - P1)/32  (both passes f32-acc HMMA)
//   LayerNorm eliminated: gamma folded into weights; per-row (sum,sumsq)
//   partials emitted by j2 epilogues; mu/r applied affinely in j0 epilogue
//   and in the residual reconstruction of the next j2.
// ============================================================================

#define NTOK    16384
#define DMODEL  1024
#define NLAYER  18

__device__ __half g_WH[(size_t)NLAYER * DMODEL * DMODEL];
__device__ __half g_WV[(size_t)NLAYER * DMODEL * DMODEL];
__device__ __half g_XH[3][(size_t)NTOK * DMODEL];
__device__ __half g_XU[3][(size_t)NTOK * DMODEL];
__device__ float  g_C[NLAYER * DMODEL];        // c_o = sum_i w'_oi (fold layers)
__device__ float  g_BIAS2[NLAYER * DMODEL];    // bias + sum_i beta_i w_oi
__device__ float  g_PART[2 * (size_t)NTOK * 16];  // [buf][row][cta*2 + {s,q}]

// ---------------- helpers ----------------------------------------------------
__device__ __forceinline__ uint32_t smem_u32(const void* p) {
    uint32_t a;
    asm("{ .reg .u64 t; cvta.to.shared.u64 t, %1; cvt.u32.u64 %0, t; }"
        : "=r"(a) : "l"(p));
    return a;
}

__device__ __forceinline__ void ldsm_x4(uint32_t* r, uint32_t addr) {
    asm volatile("ldmatrix.sync.aligned.m8n8.x4.shared.b16 {%0,%1,%2,%3}, [%4];"
                 : "=r"(r[0]), "=r"(r[1]), "=r"(r[2]), "=r"(r[3]) : "r"(addr));
}

__device__ __forceinline__ void mma_f32(float* c, const uint32_t* a,
                                        uint32_t b0, uint32_t b1) {
    asm volatile(
        "mma.sync.aligned.m16n8k16.row.col.f32.f16.f16.f32 "
        "{%0,%1,%2,%3}, {%4,%5,%6,%7}, {%8,%9}, {%0,%1,%2,%3};"
        : "+f"(c[0]), "+f"(c[1]), "+f"(c[2]), "+f"(c[3])
        : "r"(a[0]), "r"(a[1]), "r"(a[2]), "r"(a[3]), "r"(b0), "r"(b1));
}

#define CP_ASYNC16(dst, src) \
    asm volatile("cp.async.cg.shared.global [%0], [%1], 16;" \
                 :: "r"(dst), "l"(src))
#define CP_COMMIT() asm volatile("cp.async.commit_group;" ::: "memory")
#define CP_WAIT(n)  asm volatile("cp.async.wait_group %0;" :: "n"(n) : "memory")

__device__ __forceinline__ void splitHU(float v, __half& h, __half& u) {
    h = __float2half_rn(v);
    float hf = __half2float(h);
    u = __float2half_rn(fmaf(32.0f, v - hf, hf));
}

__device__ __forceinline__ void split4(const float* v, uint2& hw, uint2& uw) {
    __half h[4], u[4];
    #pragma unroll
    for (int k = 0; k < 4; k++) splitHU(v[k], h[k], u[k]);
    __half2 h01; h01.x = h[0]; h01.y = h[1];
    __half2 h23; h23.x = h[2]; h23.y = h[3];
    __half2 u01; u01.x = u[0]; u01.y = u[1];
    __half2 u23; u23.x = u[2]; u23.y = u[3];
    hw.x = *reinterpret_cast<uint32_t*>(&h01);
    hw.y = *reinterpret_cast<uint32_t*>(&h23);
    uw.x = *reinterpret_cast<uint32_t*>(&u01);
    uw.y = *reinterpret_cast<uint32_t*>(&u23);
}

// ============================================================================
// Prep: W_eff = dequant4bit + B@A; fold gamma (layers 3,6,9,12,15);
//       compute c_o = sum w'_oi and bias2_o = bias_o + sum beta_i w_oi.
// ============================================================================
__global__ __launch_bounds__(256) void prep_weights(
    const int* __restrict__ qw, const float* __restrict__ scales,
    const float* __restrict__ lA, const float* __restrict__ lB,
    const float* __restrict__ bias,
    const float* __restrict__ lng, const float* __restrict__ lnb)
{
    __shared__ float sB[16 * 32];
    __shared__ float sA[32 * 256];
    __shared__ float redC[16], redD[16];
    const int li = blockIdx.y;
    const int o0 = blockIdx.x * 16;
    const int tid = threadIdx.x;
    const int lane = tid & 31;
    const bool fold = (li % 3 == 0) && (li > 0);
    const int lnIdx = li / 3 - 1;

    const float* Bl = lB + ((size_t)li * DMODEL + o0) * 32;
    for (int k = tid; k < 512; k += 256) sB[k] = Bl[k];
    if (tid < 16) { redC[tid] = 0.0f; redD[tid] = 0.0f; }

    const float* Al = lA + (size_t)li * 32 * DMODEL;
    const int*   ql = qw + (size_t)li * DMODEL * DMODEL;
    const float* sc = scales + (size_t)li * DMODEL * 64;
    __half* wh = g_WH + (size_t)li * DMODEL * DMODEL;
    __half* wv = g_WV + (size_t)li * DMODEL * DMODEL;

    float cs[16], ds[16];
    #pragma unroll
    for (int oo = 0; oo < 16; oo++) { cs[oo] = 0.0f; ds[oo] = 0.0f; }

    for (int ic = 0; ic < 4; ic++) {
        const int i0 = ic * 256;
        __syncthreads();
        for (int k = tid; k < 8192; k += 256) {
            int r = k >> 8, c = k & 255;
            sA[r * 256 + c] = Al[(size_t)r * DMODEL + i0 + c];
        }
        __syncthreads();
        const int i = i0 + tid;
        const float gi = fold ? lng[lnIdx * DMODEL + i] : 1.0f;
        const float bi = fold ? lnb[lnIdx * DMODEL + i] : 0.0f;
        float d[16];
        #pragma unroll
        for (int oo = 0; oo < 16; oo++) d[oo] = 0.0f;
        #pragma unroll
        for (int r = 0; r < 32; r++) {
            float a = sA[r * 256 + tid];
            #pragma unroll
            for (int oo = 0; oo < 16; oo++) d[oo] += sB[oo * 32 + r] * a;
        }
        #pragma unroll
        for (int oo = 0; oo < 16; oo++) {
            const int o = o0 + oo;
            float qv = (float)ql[(size_t)o * DMODEL + i];
            float s  = sc[(size_t)o * 64 + (i >> 4)];
            float w0 = (qv * (2.0f / 15.0f) - 1.0f) * s + d[oo];
            ds[oo] += bi * w0;
            float w = w0 * gi;
            cs[oo] += w;
            __half h, u;
            splitHU(w, h, u);
            wh[(size_t)o * DMODEL + i] = h;
            wv[(size_t)o * DMODEL + i] = u;
        }
    }
    __syncthreads();
    #pragma unroll
    for (int oo = 0; oo < 16; oo++) {
        float v = cs[oo], w = ds[oo];
        #pragma unroll
        for (int o = 16; o > 0; o >>= 1) {
            v += __shfl_xor_sync(0xFFFFFFFFu, v, o);
            w += __shfl_xor_sync(0xFFFFFFFFu, w, o);
        }
        if (lane == 0) {
            atomicAdd(&redC[oo], v);
            atomicAdd(&redD[oo], w);
        }
    }
    __syncthreads();
    if (tid < 16) {
        g_C[li * DMODEL + o0 + tid] = redC[tid];
        g_BIAS2[li * DMODEL + o0 + tid] =
            bias[li * DMODEL + o0 + tid] + redD[tid];
    }
}

// ============================================================================
// Split initial x into (h, u) -> set 2
// ============================================================================
__global__ __launch_bounds__(256) void split_x(const float* __restrict__ x) {
    size_t i = ((size_t)blockIdx.x * 256 + threadIdx.x) * 4;
    float4 v4 = *reinterpret_cast<const float4*>(x + i);
    float v[4] = {v4.x, v4.y, v4.z, v4.w};
    uint2 hw, uw;
    split4(v, hw, uw);
    *reinterpret_cast<uint2*>(&g_XH[2][i]) = hw;
    *reinterpret_cast<uint2*>(&g_XU[2][i]) = uw;
}

// ============================================================================
// Main GEMM (mainloop identical to R11 — at HMMA roofline).
//   mode 0: y = [fold: r*(P-mu*c)] + b2 ; relu; split -> set outSel
//   mode 1: s = y+b2+res ; split -> set2 ; emit (sum,sumsq) partials
//   mode 2: same as 1 but fp32 -> dout, no partials
//   residual: statsIn>=0 -> LN(set2) via stats+gamma/beta ; else raw resx
// ============================================================================
#define BM 128
#define BN 128
#define BK 64
#define ROWB 128
#define TILEB (128 * ROWB)
#define STAGEB (4 * TILEB)
#define GEMM_SMEM (3 * STAGEB)
#define NCHUNK (DMODEL / BK)

__global__ __launch_bounds__(512, 1)
void qlora_gemm(int li, int inSel, int outSel, int mode, int useLN,
                int statsInIdx, int statsOutIdx, int lnIdx,
                const float* __restrict__ lng, const float* __restrict__ lnb,
                const float* __restrict__ resx, float* __restrict__ dout)
{
    extern __shared__ char smem[];
    const uint32_t sb = smem_u32(smem);
    const int tid = threadIdx.x;
    const int wid = tid >> 5;
    const int lane = tid & 31;
    const int warp_m = wid & 3;
    const int warp_n = wid >> 2;
    const int m0 = blockIdx.y * BM;
    const int n0 = blockIdx.x * BN;

    const __half* xh = g_XH[inSel];
    const __half* xu = g_XU[inSel];
    const __half* whp = g_WH + (size_t)li * DMODEL * DMODEL;
    const __half* wvp = g_WV + (size_t)li * DMODEL * DMODEL;

    const int r0 = tid >> 3;
    const int c8 = tid & 7;
    const uint32_t dloc = (uint32_t)(r0 * ROWB + ((c8 ^ (r0 & 7)) * 16));
    const char* P0p = (const char*)(xh + (size_t)m0 * DMODEL) + r0 * 2048 + c8 * 16;
    const char* P1p = (const char*)(xu + (size_t)m0 * DMODEL) + r0 * 2048 + c8 * 16;
    const char* P2p = (const char*)(whp + (size_t)n0 * DMODEL) + r0 * 2048 + c8 * 16;
    const char* P3p = (const char*)(wvp + (size_t)n0 * DMODEL) + r0 * 2048 + c8 * 16;

    const int lrow = lane & 15;
    const int lch  = lane >> 4;
    const int swz  = lrow & 7;
    const uint32_t co0 = (uint32_t)(((lch + 0) ^ swz) * 16);
    const uint32_t co1 = (uint32_t)(((lch + 2) ^ swz) * 16);
    const uint32_t co2 = (uint32_t)(((lch + 4) ^ swz) * 16);
    const uint32_t co3 = (uint32_t)(((lch + 6) ^ swz) * 16);
    const uint32_t rowA = (uint32_t)((warp_m * 32 + lrow) * ROWB);
    const uint32_t rowB = (uint32_t)((warp_n * 32 + lrow) * ROWB);

    float acc[2][4][4];
    float accu[2][4][4];
    #pragma unroll
    for (int a = 0; a < 2; a++)
        #pragma unroll
        for (int b = 0; b < 4; b++)
            #pragma unroll
            for (int q = 0; q < 4; q++) { acc[a][b][q] = 0.0f; accu[a][b][q] = 0.0f; }

#define LOADC(kc, ST) do {                                                     \
    const uint32_t _sb2 = sb + (ST) * STAGEB + dloc;                           \
    const size_t _ko = (size_t)(kc) * 128;                                     \
    CP_ASYNC16(_sb2,                          P0p + _ko);                      \
    CP_ASYNC16(_sb2 + 8192,                   P0p + _ko + 131072);             \
    CP_ASYNC16(_sb2 + TILEB,                  P1p + _ko);                      \
    CP_ASYNC16(_sb2 + TILEB + 8192,           P1p + _ko + 131072);             \
    CP_ASYNC16(_sb2 + 2 * TILEB,              P2p + _ko);                      \
    CP_ASYNC16(_sb2 + 2 * TILEB + 8192,       P2p + _ko + 131072);             \
    CP_ASYNC16(_sb2 + 3 * TILEB,              P3p + _ko);                      \
    CP_ASYNC16(_sb2 + 3 * TILEB + 8192,       P3p + _ko + 131072);             \
    CP_COMMIT();                                                               \
} while (0)

#define MMASTEP(BASE, CO) do {                                                 \
    uint32_t fxh[2][4], fxu[2][4], fwh[2][4], fwv[2][4];                       \
    _Pragma("unroll")                                                          \
    for (int mi = 0; mi < 2; mi++)                                             \
        ldsm_x4(fxh[mi], (BASE) + rowA + mi * (16 * ROWB) + (CO));             \
    _Pragma("unroll")                                                          \
    for (int nj = 0; nj < 2; nj++)                                             \
        ldsm_x4(fwh[nj], (BASE) + 2 * TILEB + rowB + nj * (16 * ROWB) + (CO)); \
    _Pragma("unroll")                                                          \
    for (int mi = 0; mi < 2; mi++)                                             \
        ldsm_x4(fxu[mi], (BASE) + TILEB + rowA + mi * (16 * ROWB) + (CO));     \
    _Pragma("unroll")                                                          \
    for (int nj = 0; nj < 2; nj++)                                             \
        ldsm_x4(fwv[nj], (BASE) + 3 * TILEB + rowB + nj * (16 * ROWB) + (CO)); \
    _Pragma("unroll")                                                          \
    for (int mi = 0; mi < 2; mi++)                                             \
        _Pragma("unroll")                                                      \
        for (int ni = 0; ni < 4; ni++) {                                       \
            const int nj = ni >> 1, s2 = ni & 1;                               \
            mma_f32(acc[mi][ni], fxh[mi], fwh[nj][s2], fwh[nj][s2 + 2]);       \
        }                                                                      \
    _Pragma("unroll")                                                          \
    for (int mi = 0; mi < 2; mi++)                                             \
        _Pragma("unroll")                                                      \
        for (int ni = 0; ni < 4; ni++) {                                       \
            const int nj = ni >> 1, s2 = ni & 1;                               \
            mma_f32(accu[mi][ni], fxu[mi], fwv[nj][s2], fwv[nj][s2 + 2]);      \
        }                                                                      \
} while (0)

#define CHUNK(kc, ST, DO_LOAD) do {                                            \
    CP_WAIT(1);                                                                \
    __syncthreads();                                                           \
    if (DO_LOAD) { LOADC((kc) + 2, ((ST) + 2) % 3); } else { CP_COMMIT(); }    \
    const uint32_t _base = sb + (ST) * STAGEB;                                 \
    MMASTEP(_base, co0);                                                       \
    MMASTEP(_base, co1);                                                       \
    MMASTEP(_base, co2);                                                       \
    MMASTEP(_base, co3);                                                       \
} while (0)

    LOADC(0, 0);
    LOADC(1, 1);

    #pragma unroll 1
    for (int k3 = 0; k3 < 12; k3 += 3) {
        CHUNK(k3 + 0, 0, true);
        CHUNK(k3 + 1, 1, true);
        CHUNK(k3 + 2, 2, true);
    }
    CHUNK(12, 0, true);
    CHUNK(13, 1, true);
    CHUNK(14, 2, false);
    CHUNK(15, 0, false);

#undef CHUNK
#undef MMASTEP
#undef LOADC

    // ---------------- epilogue ------------------------------------------------
    const float* bias2c = g_BIAS2 + li * DMODEL;
    const float* cvec   = g_C + li * DMODEL;
    const float* statsPart = (statsInIdx >= 0)
        ? g_PART + (size_t)statsInIdx * NTOK * 16 : nullptr;
    float* partOut = (statsOutIdx >= 0)
        ? g_PART + (size_t)statsOutIdx * NTOK * 16 : nullptr;
    const float* gam = (lnIdx >= 0) ? lng + lnIdx * DMODEL : nullptr;
    const float* bet = (lnIdx >= 0) ? lnb + lnIdx * DMODEL : nullptr;
    const bool haveStats = (statsPart != nullptr);

    __syncthreads();                       // stage smem free for reuse
    float* smu = reinterpret_cast<float*>(smem);   // [128][2]
    float* sS  = smu + 256;                         // [128][4]
    float* sQ  = sS + 512;                          // [128][4]

    if (haveStats && tid < 128) {
        const size_t row = (size_t)(m0 + tid);
        float s = 0.0f, q = 0.0f;
        #pragma unroll
        for (int j = 0; j < 8; j++) {
            s += statsPart[row * 16 + j * 2];
            q += statsPart[row * 16 + j * 2 + 1];
        }
        float mu = s * (1.0f / DMODEL);
        float var = q * (1.0f / DMODEL) - mu * mu;
        smu[tid * 2]     = mu;
        smu[tid * 2 + 1] = rsqrtf(var + 1e-5f);
    }
    __syncthreads();

    const int grow = lane >> 2;
    const int gcol = (lane & 3) * 2;
    __half* outH = g_XH[outSel];
    __half* outU = g_XU[outSel];
    const __half* resH = g_XH[2];
    const __half* resU = g_XU[2];

    float pS[2][2], pQ[2][2];
    #pragma unroll
    for (int mi = 0; mi < 2; mi++)
        #pragma unroll
        for (int h = 0; h < 2; h++) { pS[mi][h] = 0.0f; pQ[mi][h] = 0.0f; }

    #pragma unroll
    for (int mi = 0; mi < 2; mi++) {
        #pragma unroll
        for (int ni = 0; ni < 4; ni++) {
            const int col = n0 + warp_n * 32 + ni * 8 + gcol;
            float2 b2 = __ldg((const float2*)(bias2c + col));
            float2 c2 = make_float2(0.0f, 0.0f);
            if (useLN) c2 = __ldg((const float2*)(cvec + col));
            float2 g2 = make_float2(1.0f, 1.0f), bb2 = make_float2(0.0f, 0.0f);
            if (mode != 0 && haveStats) {
                g2  = __ldg((const float2*)(gam + col));
                bb2 = __ldg((const float2*)(bet + col));
            }
            #pragma unroll
            for (int h = 0; h < 2; h++) {
                const int rloc = warp_m * 32 + mi * 16 + h * 8 + grow;
                const size_t row = (size_t)(m0 + rloc);
                float pa = acc[mi][ni][h * 2 + 0];
                float pb = acc[mi][ni][h * 2 + 1];
                float Pc0 = fmaf(accu[mi][ni][h * 2 + 0] - pa, 0.03125f, pa);
                float Pc1 = fmaf(accu[mi][ni][h * 2 + 1] - pb, 0.03125f, pb);
                float y0, y1;
                if (mode == 0 && useLN) {
                    float mu = smu[rloc * 2], rv = smu[rloc * 2 + 1];
                    y0 = fmaf(rv, Pc0 - mu * c2.x, b2.x);
                    y1 = fmaf(rv, Pc1 - mu * c2.y, b2.y);
                } else {
                    y0 = Pc0 + b2.x;
                    y1 = Pc1 + b2.y;
                }
                if (mode == 0) {
                    y0 = fmaxf(y0, 0.0f);
                    y1 = fmaxf(y1, 0.0f);
                    __half h0, u0, h1, u1;
                    splitHU(y0, h0, u0);
                    splitHU(y1, h1, u1);
                    __half2 hp; hp.x = h0; hp.y = h1;
                    __half2 up; up.x = u0; up.y = u1;
                    *reinterpret_cast<__half2*>(outH + row * DMODEL + col) = hp;
                    *reinterpret_cast<__half2*>(outU + row * DMODEL + col) = up;
                } else {
                    float res0, res1;
                    if (haveStats) {
                        float2 rh = __half22float2(__ldg(
                            (const __half2*)(resH + row * DMODEL + col)));
                        float2 ru = __half22float2(__ldg(
                            (const __half2*)(resU + row * DMODEL + col)));
                        float rec0 = fmaf(ru.x - rh.x, 0.03125f, rh.x);
                        float rec1 = fmaf(ru.y - rh.y, 0.03125f, rh.y);
                        float mu = smu[rloc * 2], rv = smu[rloc * 2 + 1];
                        res0 = fmaf((rec0 - mu) * rv, g2.x, bb2.x);
                        res1 = fmaf((rec1 - mu) * rv, g2.y, bb2.y);
                    } else {
                        float2 r2 = __ldg((const float2*)(resx + row * DMODEL + col));
                        res0 = r2.x;
                        res1 = r2.y;
                    }
                    float s0 = y0 + res0, s1 = y1 + res1;
                    if (mode == 1) {
                        pS[mi][h] += s0 + s1;
                        pQ[mi][h] += s0 * s0 + s1 * s1;
                        __half h0, u0, h1, u1;
                        splitHU(s0, h0, u0);
                        splitHU(s1, h1, u1);
                        __half2 hp; hp.x = h0; hp.y = h1;
                        __half2 up; up.x = u0; up.y = u1;
                        *reinterpret_cast<__half2*>(outH + row * DMODEL + col) = hp;
                        *reinterpret_cast<__half2*>(outU + row * DMODEL + col) = up;
                    } else {
                        float2 o2; o2.x = s0; o2.y = s1;
                        *reinterpret_cast<float2*>(dout + row * DMODEL + col) = o2;
                    }
                }
            }
        }
    }

    if (mode == 1) {
        #pragma unroll
        for (int mi = 0; mi < 2; mi++)
            #pragma unroll
            for (int h = 0; h < 2; h++) {
                float s = pS[mi][h], q = pQ[mi][h];
                s += __shfl_xor_sync(0xFFFFFFFFu, s, 1);
                s += __shfl_xor_sync(0xFFFFFFFFu, s, 2);
                q += __shfl_xor_sync(0xFFFFFFFFu, q, 1);
                q += __shfl_xor_sync(0xFFFFFFFFu, q, 2);
                if ((lane & 3) == 0) {
                    int rloc = warp_m * 32 + mi * 16 + h * 8 + grow;
                    sS[rloc * 4 + warp_n] = s;
                    sQ[rloc * 4 + warp_n] = q;
                }
            }
        __syncthreads();
        if (tid < 128) {
            float s = sS[tid * 4] + sS[tid * 4 + 1] + sS[tid * 4 + 2] + sS[tid * 4 + 3];
            float q = sQ[tid * 4] + sQ[tid * 4 + 1] + sQ[tid * 4 + 2] + sQ[tid * 4 + 3];
            partOut[(size_t)(m0 + tid) * 16 + blockIdx.x * 2]     = s;
            partOut[(size_t)(m0 + tid) * 16 + blockIdx.x * 2 + 1] = q;
        }
    }
}

// ============================================================================
// Launch
// ============================================================================
extern "C" void kernel_launch(void* const* d_in, const int* in_sizes, int n_in,
                              void* d_out, int out_size)
{
    (void)in_sizes; (void)n_in; (void)out_size;
    const float* x      = (const float*)d_in[0];
    const int*   qw     = (const int*)d_in[1];
    const float* scales = (const float*)d_in[2];
    const float* bias   = (const float*)d_in[3];
    const float* lA     = (const float*)d_in[4];
    const float* lB     = (const float*)d_in[5];
    const float* lng    = (const float*)d_in[6];
    const float* lnb    = (const float*)d_in[7];
    float* out = (float*)d_out;

    cudaFuncSetAttribute(qlora_gemm, cudaFuncAttributeMaxDynamicSharedMemorySize,
                         GEMM_SMEM);

    prep_weights<<<dim3(64, 18), 256>>>(qw, scales, lA, lB, bias, lng, lnb);
    split_x<<<(NTOK * DMODEL) / 1024, 256>>>(x);

    for (int blk = 0; blk < 6; blk++) {
        const int l0 = blk * 3;
        const int stIn  = (blk > 0) ? ((blk - 1) & 1) : -1;
        // j0: set2 -> set0 (LN folded for blk>0)
        qlora_gemm<<<dim3(8, 128), 512, GEMM_SMEM>>>(
            l0 + 0, 2, 0, 0, (blk > 0) ? 1 : 0,
            stIn, -1, -1, lng, lnb, nullptr, nullptr);
        // j1: set0 -> set1
        qlora_gemm<<<dim3(8, 128), 512, GEMM_SMEM>>>(
            l0 + 1, 0, 1, 0, 0,
            -1, -1, -1, lng, lnb, nullptr, nullptr);
        // j2: set1 + residual -> set2 (+stats) or dout
        if (blk < 5) {
            qlora_gemm<<<dim3(8, 128), 512, GEMM_SMEM>>>(
                l0 + 2, 1, 2, 1, 0,
                stIn, blk & 1, blk - 1, lng, lnb, x, nullptr);
        } else {
            qlora_gemm<<<dim3(8, 128), 512, GEMM_SMEM>>>(
                l0 + 2, 1, 2, 2, 0,
                stIn, -1, blk - 1, lng, lnb, nullptr, out);
        }
    }
}

// round 14
// speedup vs baseline: 1.0537x; 1.0537x over previous
#include <cuda_runtime.h>
#include <cuda_fp16.h>
#include <cstdint>

// ============================================================================
// QLoRABigNet on GB300 (mma.sync fp16, 2-pass Karatsuba split)  [R11 revert]
//   activations/weights stored as (h, u):  h = fl16(x), u = fl16(h + 32*(x-h))
//   y = P1 + (P2 - P1)/32,  P1 = xh.wh, P2 = u.v   (both f32-acc HMMA)
//   -> 16 MMA/k16-step; GEMM at ~95% of measured HMMA roofline.
// ============================================================================

#define NTOK    16384
#define DMODEL  1024
#define NLAYER  18

__device__ __half g_WH[(size_t)NLAYER * DMODEL * DMODEL];
__device__ __half g_WV[(size_t)NLAYER * DMODEL * DMODEL];
__device__ __half g_XH[3][(size_t)NTOK * DMODEL];
__device__ __half g_XU[3][(size_t)NTOK * DMODEL];
__device__ float  g_TMP[(size_t)NTOK * DMODEL];

// ---------------- helpers ----------------------------------------------------
__device__ __forceinline__ uint32_t smem_u32(const void* p) {
    uint32_t a;
    asm("{ .reg .u64 t; cvta.to.shared.u64 t, %1; cvt.u32.u64 %0, t; }"
        : "=r"(a) : "l"(p));
    return a;
}

__device__ __forceinline__ void ldsm_x4(uint32_t* r, uint32_t addr) {
    asm volatile("ldmatrix.sync.aligned.m8n8.x4.shared.b16 {%0,%1,%2,%3}, [%4];"
                 : "=r"(r[0]), "=r"(r[1]), "=r"(r[2]), "=r"(r[3]) : "r"(addr));
}

// f16 inputs, f32 accumulators
__device__ __forceinline__ void mma_f32(float* c, const uint32_t* a,
                                        uint32_t b0, uint32_t b1) {
    asm volatile(
        "mma.sync.aligned.m16n8k16.row.col.f32.f16.f16.f32 "
        "{%0,%1,%2,%3}, {%4,%5,%6,%7}, {%8,%9}, {%0,%1,%2,%3};"
        : "+f"(c[0]), "+f"(c[1]), "+f"(c[2]), "+f"(c[3])
        : "r"(a[0]), "r"(a[1]), "r"(a[2]), "r"(a[3]), "r"(b0), "r"(b1));
}

#define CP_ASYNC16(dst, src) \
    asm volatile("cp.async.cg.shared.global [%0], [%1], 16;" \
                 :: "r"(dst), "l"(src))
#define CP_COMMIT() asm volatile("cp.async.commit_group;" ::: "memory")
#define CP_WAIT(n)  asm volatile("cp.async.wait_group %0;" :: "n"(n) : "memory")

// split value into (h, u): h = fl16(v), u = fl16(h + 32*(v - h))
__device__ __forceinline__ void splitHU(float v, __half& h, __half& u) {
    h = __float2half_rn(v);
    float hf = __half2float(h);
    u = __float2half_rn(fmaf(32.0f, v - hf, hf));
}

// pack 4 floats -> (h half2x2, u half2x2) as uint2 each
__device__ __forceinline__ void split4(const float* v, uint2& hw, uint2& uw) {
    __half h[4], u[4];
    #pragma unroll
    for (int k = 0; k < 4; k++) splitHU(v[k], h[k], u[k]);
    __half2 h01; h01.x = h[0]; h01.y = h[1];
    __half2 h23; h23.x = h[2]; h23.y = h[3];
    __half2 u01; u01.x = u[0]; u01.y = u[1];
    __half2 u23; u23.x = u[2]; u23.y = u[3];
    hw.x = *reinterpret_cast<uint32_t*>(&h01);
    hw.y = *reinterpret_cast<uint32_t*>(&h23);
    uw.x = *reinterpret_cast<uint32_t*>(&u01);
    uw.y = *reinterpret_cast<uint32_t*>(&u23);
}

// ============================================================================
// Prep: W_eff = dequant4bit + B@A, split into (wh, wv)
// ============================================================================
__global__ __launch_bounds__(256) void prep_weights(
    const int* __restrict__ qw, const float* __restrict__ scales,
    const float* __restrict__ lA, const float* __restrict__ lB)
{
    __shared__ float sB[16 * 32];
    __shared__ float sA[32 * 256];
    const int li = blockIdx.y;
    const int o0 = blockIdx.x * 16;
    const int tid = threadIdx.x;

    const float* Bl = lB + ((size_t)li * DMODEL + o0) * 32;
    for (int k = tid; k < 512; k += 256) sB[k] = Bl[k];

    const float* Al = lA + (size_t)li * 32 * DMODEL;
    const int*   ql = qw + (size_t)li * DMODEL * DMODEL;
    const float* sc = scales + (size_t)li * DMODEL * 64;
    __half* wh = g_WH + (size_t)li * DMODEL * DMODEL;
    __half* wv = g_WV + (size_t)li * DMODEL * DMODEL;

    for (int ic = 0; ic < 4; ic++) {
        const int i0 = ic * 256;
        __syncthreads();
        for (int k = tid; k < 8192; k += 256) {
            int r = k >> 8, c = k & 255;
            sA[r * 256 + c] = Al[(size_t)r * DMODEL + i0 + c];
        }
        __syncthreads();
        const int i = i0 + tid;
        float d[16];
        #pragma unroll
        for (int oo = 0; oo < 16; oo++) d[oo] = 0.0f;
        #pragma unroll
        for (int r = 0; r < 32; r++) {
            float a = sA[r * 256 + tid];
            #pragma unroll
            for (int oo = 0; oo < 16; oo++) d[oo] += sB[oo * 32 + r] * a;
        }
        #pragma unroll
        for (int oo = 0; oo < 16; oo++) {
            const int o = o0 + oo;
            float qv = (float)ql[(size_t)o * DMODEL + i];
            float s  = sc[(size_t)o * 64 + (i >> 4)];
            float w  = (qv * (2.0f / 15.0f) - 1.0f) * s + d[oo];
            __half h, u;
            splitHU(w, h, u);
            wh[(size_t)o * DMODEL + i] = h;
            wv[(size_t)o * DMODEL + i] = u;
        }
    }
}

// ============================================================================
// Split initial x into (h, u) -> set 2
// ============================================================================
__global__ __launch_bounds__(256) void split_x(const float* __restrict__ x) {
    size_t i = ((size_t)blockIdx.x * 256 + threadIdx.x) * 4;
    float4 v4 = *reinterpret_cast<const float4*>(x + i);
    float v[4] = {v4.x, v4.y, v4.z, v4.w};
    uint2 hw, uw;
    split4(v, hw, uw);
    *reinterpret_cast<uint2*>(&g_XH[2][i]) = hw;
    *reinterpret_cast<uint2*>(&g_XU[2][i]) = uw;
}

// ============================================================================
// Main GEMM: CTA tile 128x128, 512 threads (16 warps, warp tile 32x32),
//   BK=64, 3-stage cp.async; P1 = xh.wh, P2 = xu.wv, both f32-acc.
//   SMEM: 128B rows, swizzle chunk ^= row&7; 192KB, 1 CTA/SM
//   mode 0: relu(y+b) -> (h,u) into set outSel
//   mode 1: y+b+res(set2) -> g_TMP
//   mode 2: y+b+res(set2) -> dout
// ============================================================================
#define BM 128
#define BN 128
#define BK 64
#define ROWB 128
#define TILEB (128 * ROWB)        // 16384 B
#define STAGEB (4 * TILEB)        // 65536 B
#define GEMM_SMEM (3 * STAGEB)    // 196608 B
#define NCHUNK (DMODEL / BK)      // 16

__global__ __launch_bounds__(512, 1)
void qlora_gemm(int li, int inSel, int outSel, int mode,
                const float* __restrict__ bias,
                float* __restrict__ dout)
{
    extern __shared__ char smem[];
    const uint32_t sb = smem_u32(smem);
    const int tid = threadIdx.x;
    const int wid = tid >> 5;
    const int lane = tid & 31;
    const int warp_m = wid & 3;
    const int warp_n = wid >> 2;
    const int m0 = blockIdx.y * BM;
    const int n0 = blockIdx.x * BN;

    const __half* xh = g_XH[inSel];
    const __half* xu = g_XU[inSel];
    const __half* whp = g_WH + (size_t)li * DMODEL * DMODEL;
    const __half* wvp = g_WV + (size_t)li * DMODEL * DMODEL;

    // --------- hoisted cp.async addressing ----------------------------------
    const int r0 = tid >> 3;          // 0..63
    const int c8 = tid & 7;           // 0..7
    const uint32_t dloc = (uint32_t)(r0 * ROWB + ((c8 ^ (r0 & 7)) * 16));
    const char* P0 = (const char*)(xh + (size_t)m0 * DMODEL) + r0 * 2048 + c8 * 16;
    const char* P1 = (const char*)(xu + (size_t)m0 * DMODEL) + r0 * 2048 + c8 * 16;
    const char* P2 = (const char*)(whp + (size_t)n0 * DMODEL) + r0 * 2048 + c8 * 16;
    const char* P3 = (const char*)(wvp + (size_t)n0 * DMODEL) + r0 * 2048 + c8 * 16;

    // per-lane ldmatrix components
    const int lrow = lane & 15;
    const int lch  = lane >> 4;       // 0/1
    const int swz  = lrow & 7;
    const uint32_t co0 = (uint32_t)(((lch + 0) ^ swz) * 16);
    const uint32_t co1 = (uint32_t)(((lch + 2) ^ swz) * 16);
    const uint32_t co2 = (uint32_t)(((lch + 4) ^ swz) * 16);
    const uint32_t co3 = (uint32_t)(((lch + 6) ^ swz) * 16);
    const uint32_t rowA = (uint32_t)((warp_m * 32 + lrow) * ROWB);
    const uint32_t rowB = (uint32_t)((warp_n * 32 + lrow) * ROWB);

    float acc[2][4][4];          // P1: xh.wh
    float accu[2][4][4];         // P2: xu.wv
    #pragma unroll
    for (int a = 0; a < 2; a++)
        #pragma unroll
        for (int b = 0; b < 4; b++)
            #pragma unroll
            for (int q = 0; q < 4; q++) { acc[a][b][q] = 0.0f; accu[a][b][q] = 0.0f; }

// load chunk kc into stage ST (compile-time literal): 8 vectors/thread
#define LOADC(kc, ST) do {                                                     \
    const uint32_t _sb2 = sb + (ST) * STAGEB + dloc;                           \
    const size_t _ko = (size_t)(kc) * 128;                                     \
    CP_ASYNC16(_sb2,                          P0 + _ko);                       \
    CP_ASYNC16(_sb2 + 8192,                   P0 + _ko + 131072);              \
    CP_ASYNC16(_sb2 + TILEB,                  P1 + _ko);                       \
    CP_ASYNC16(_sb2 + TILEB + 8192,           P1 + _ko + 131072);              \
    CP_ASYNC16(_sb2 + 2 * TILEB,              P2 + _ko);                       \
    CP_ASYNC16(_sb2 + 2 * TILEB + 8192,       P2 + _ko + 131072);              \
    CP_ASYNC16(_sb2 + 3 * TILEB,              P3 + _ko);                       \
    CP_ASYNC16(_sb2 + 3 * TILEB + 8192,       P3 + _ko + 131072);              \
    CP_COMMIT();                                                               \
} while (0)

// one k16 step: 8 ldsm.x4; 8 + 8 f32-acc MMAs
#define MMASTEP(BASE, CO) do {                                                 \
    uint32_t fxh[2][4], fxu[2][4], fwh[2][4], fwv[2][4];                       \
    _Pragma("unroll")                                                          \
    for (int mi = 0; mi < 2; mi++)                                             \
        ldsm_x4(fxh[mi], (BASE) + rowA + mi * (16 * ROWB) + (CO));             \
    _Pragma("unroll")                                                          \
    for (int nj = 0; nj < 2; nj++)                                             \
        ldsm_x4(fwh[nj], (BASE) + 2 * TILEB + rowB + nj * (16 * ROWB) + (CO)); \
    _Pragma("unroll")                                                          \
    for (int mi = 0; mi < 2; mi++)                                             \
        ldsm_x4(fxu[mi], (BASE) + TILEB + rowA + mi * (16 * ROWB) + (CO));     \
    _Pragma("unroll")                                                          \
    for (int nj = 0; nj < 2; nj++)                                             \
        ldsm_x4(fwv[nj], (BASE) + 3 * TILEB + rowB + nj * (16 * ROWB) + (CO)); \
    _Pragma("unroll")                                                          \
    for (int mi = 0; mi < 2; mi++)                                             \
        _Pragma("unroll")                                                      \
        for (int ni = 0; ni < 4; ni++) {                                       \
            const int nj = ni >> 1, s2 = ni & 1;                               \
            mma_f32(acc[mi][ni], fxh[mi], fwh[nj][s2], fwh[nj][s2 + 2]);       \
        }                                                                      \
    _Pragma("unroll")                                                          \
    for (int mi = 0; mi < 2; mi++)                                             \
        _Pragma("unroll")                                                      \
        for (int ni = 0; ni < 4; ni++) {                                       \
            const int nj = ni >> 1, s2 = ni & 1;                               \
            mma_f32(accu[mi][ni], fxu[mi], fwv[nj][s2], fwv[nj][s2 + 2]);      \
        }                                                                      \
} while (0)

// chunk: wait own groups -> barrier publishes all -> prefetch -> 4 k16 steps
#define CHUNK(kc, ST, DO_LOAD) do {                                            \
    CP_WAIT(1);                                                                \
    __syncthreads();                                                           \
    if (DO_LOAD) { LOADC((kc) + 2, ((ST) + 2) % 3); } else { CP_COMMIT(); }    \
    const uint32_t _base = sb + (ST) * STAGEB;                                 \
    MMASTEP(_base, co0);                                                       \
    MMASTEP(_base, co1);                                                       \
    MMASTEP(_base, co2);                                                       \
    MMASTEP(_base, co3);                                                       \
} while (0)

    LOADC(0, 0);
    LOADC(1, 1);

    #pragma unroll 1
    for (int k3 = 0; k3 < 12; k3 += 3) {
        CHUNK(k3 + 0, 0, true);
        CHUNK(k3 + 1, 1, true);
        CHUNK(k3 + 2, 2, true);
    }
    CHUNK(12, 0, true);
    CHUNK(13, 1, true);
    CHUNK(14, 2, false);
    CHUNK(15, 0, false);

#undef CHUNK
#undef MMASTEP
#undef LOADC

    // ---------------- epilogue ------------------------------------------------
    const int grow = lane >> 2;
    const int gcol = (lane & 3) * 2;
    __half* outH = g_XH[outSel];
    __half* outU = g_XU[outSel];
    const __half* resH = g_XH[2];
    const __half* resU = g_XU[2];
    float* outF = (mode == 2) ? dout : g_TMP;

    #pragma unroll
    for (int mi = 0; mi < 2; mi++) {
        const int r0e = m0 + warp_m * 32 + mi * 16 + grow;
        #pragma unroll
        for (int ni = 0; ni < 4; ni++) {
            const int col = n0 + warp_n * 32 + ni * 8 + gcol;
            float2 b2 = __ldg((const float2*)(bias + col));
            #pragma unroll
            for (int half = 0; half < 2; half++) {
                const int row = r0e + half * 8;
                float p0 = acc[mi][ni][half * 2 + 0];
                float p1 = acc[mi][ni][half * 2 + 1];
                // y = P1 + (P2-P1)/32
                float v0 = fmaf(accu[mi][ni][half * 2 + 0] - p0, 0.03125f, p0) + b2.x;
                float v1 = fmaf(accu[mi][ni][half * 2 + 1] - p1, 0.03125f, p1) + b2.y;
                if (mode == 0) {
                    v0 = fmaxf(v0, 0.0f);
                    v1 = fmaxf(v1, 0.0f);
                    __half h0, u0, h1, u1;
                    splitHU(v0, h0, u0);
                    splitHU(v1, h1, u1);
                    __half2 hp; hp.x = h0; hp.y = h1;
                    __half2 up; up.x = u0; up.y = u1;
                    *reinterpret_cast<__half2*>(outH + (size_t)row * DMODEL + col) = hp;
                    *reinterpret_cast<__half2*>(outU + (size_t)row * DMODEL + col) = up;
                } else {
                    // residual x = h + (u-h)/32
                    float2 rh = __half22float2(__ldg(
                        (const __half2*)(resH + (size_t)row * DMODEL + col)));
                    float2 ru = __half22float2(__ldg(
                        (const __half2*)(resU + (size_t)row * DMODEL + col)));
                    float2 o2;
                    o2.x = v0 + fmaf(ru.x - rh.x, 0.03125f, rh.x);
                    o2.y = v1 + fmaf(ru.y - rh.y, 0.03125f, rh.y);
                    *reinterpret_cast<float2*>(outF + (size_t)row * DMODEL + col) = o2;
                }
            }
        }
    }
}

// ============================================================================
// LayerNorm: 1 block (256 thr) per token row; g_TMP -> set 2 (h,u)
// ============================================================================
__global__ __launch_bounds__(256) void ln_kernel(
    const float* __restrict__ gamma, const float* __restrict__ beta)
{
    const int row = blockIdx.x;
    const int tid = threadIdx.x;
    const int wid = tid >> 5, lane = tid & 31;

    float4 v4 = __ldg(reinterpret_cast<const float4*>(
        g_TMP + (size_t)row * DMODEL) + tid);
    float v[4] = {v4.x, v4.y, v4.z, v4.w};

    float s  = v[0] + v[1] + v[2] + v[3];
    float s2 = v[0] * v[0] + v[1] * v[1] + v[2] * v[2] + v[3] * v[3];
    #pragma unroll
    for (int o = 16; o > 0; o >>= 1) {
        s  += __shfl_xor_sync(0xFFFFFFFFu, s, o);
        s2 += __shfl_xor_sync(0xFFFFFFFFu, s2, o);
    }
    __shared__ float redS[8], redQ[8];
    if (lane == 0) { redS[wid] = s; redQ[wid] = s2; }
    __syncthreads();
    float tot = 0.0f, totq = 0.0f;
    #pragma unroll
    for (int w = 0; w < 8; w++) { tot += redS[w]; totq += redQ[w]; }
    const float mean = tot * (1.0f / DMODEL);
    const float var  = totq * (1.0f / DMODEL) - mean * mean;
    const float r    = rsqrtf(var + 1e-5f);

    float4 g4 = __ldg(reinterpret_cast<const float4*>(gamma) + tid);
    float4 b4 = __ldg(reinterpret_cast<const float4*>(beta) + tid);
    float gg[4] = {g4.x, g4.y, g4.z, g4.w};
    float bb[4] = {b4.x, b4.y, b4.z, b4.w};

    float y[4];
    #pragma unroll
    for (int k = 0; k < 4; k++)
        y[k] = (v[k] - mean) * r * gg[k] + bb[k];

    uint2 hw, uw;
    split4(y, hw, uw);
    const size_t off = (size_t)row * DMODEL + tid * 4;
    *reinterpret_cast<uint2*>(&g_XH[2][off]) = hw;
    *reinterpret_cast<uint2*>(&g_XU[2][off]) = uw;
}

// ============================================================================
// Launch
// ============================================================================
extern "C" void kernel_launch(void* const* d_in, const int* in_sizes, int n_in,
                              void* d_out, int out_size)
{
    (void)in_sizes; (void)n_in; (void)out_size;
    const float* x      = (const float*)d_in[0];
    const int*   qw     = (const int*)d_in[1];
    const float* scales = (const float*)d_in[2];
    const float* bias   = (const float*)d_in[3];
    const float* lA     = (const float*)d_in[4];
    const float* lB     = (const float*)d_in[5];
    const float* lng    = (const float*)d_in[6];
    const float* lnb    = (const float*)d_in[7];
    float* out = (float*)d_out;

    cudaFuncSetAttribute(qlora_gemm, cudaFuncAttributeMaxDynamicSharedMemorySize,
                         GEMM_SMEM);

    prep_weights<<<dim3(64, 18), 256>>>(qw, scales, lA, lB);
    split_x<<<(NTOK * DMODEL) / 1024, 256>>>(x);

    for (int blk = 0; blk < 6; blk++) {
        const int l0 = blk * 3;
        // j=0: set2 -> set0
        qlora_gemm<<<dim3(8, 128), 512, GEMM_SMEM>>>(
            l0 + 0, 2, 0, 0, bias + (l0 + 0) * DMODEL, nullptr);
        // j=1: set0 -> set1
        qlora_gemm<<<dim3(8, 128), 512, GEMM_SMEM>>>(
            l0 + 1, 0, 1, 0, bias + (l0 + 1) * DMODEL, nullptr);
        // j=2: set1 + residual(set2) -> TMP or out
        const int mode = (blk == 5) ? 2 : 1;
        qlora_gemm<<<dim3(8, 128), 512, GEMM_SMEM>>>(
            l0 + 2, 1, 0, mode, bias + (l0 + 2) * DMODEL, out);
        if (blk < 5) ln_kernel<<<NTOK, 256>>>(lng + blk * DMODEL, lnb + blk * DMODEL);
    }
}